// round 5
// baseline (speedup 1.0000x reference)
#include <cuda_runtime.h>
#include <cstdint>

// SkeletonLinear: out = x @ (W .* M)^T + b
// x: [32768, 768] f32, W/M: [768, 768] f32, b: [768], out: [32768, 768] f32
// Block-sparse mask: dst node d reads src nodes {d-1, d} only (24 nodes x 32ch).
//
// R5 (= R4 + warp-offset fix): CTA = 64 thr / 128 rows / 1 node. Thread tile =
// 8 rows x 8 outputs (smem-return-bandwidth balance point). x staged transposed
// with XOR swizzle on the low row bits; w staged k2-major with o-groups padded
// to 80B. Compute x-read index now includes warp*64 (the R4 bug).

#define NODES   24
#define CH      32
#define DIM     768
#define BATCH   32768
#define ROWS    128
#define THREADS 64

#define XK      132   // float2 stride per k2 row of xs (128 + pad 4)
#define WK      40    // float2 stride per k2 row of ws (4 o_grps * 10)

__device__ __forceinline__ void ffma2(unsigned long long& acc,
                                      unsigned long long a,
                                      unsigned long long b) {
    asm("fma.rn.f32x2 %0, %1, %2, %0;" : "+l"(acc) : "l"(a), "l"(b));
}

__global__ void __launch_bounds__(THREADS)
skeleton_linear_kernel(const float* __restrict__ x,
                       const float* __restrict__ w,
                       const float* __restrict__ bias,
                       const float* __restrict__ mask,
                       float* __restrict__ out) {
    const int d    = blockIdx.y;
    const int row0 = blockIdx.x * ROWS;
    const int tid  = threadIdx.x;

    // 64-col input window; mask multiply zeroes the non-edge half for d==0.
    const int col0 = (d == 0) ? 0 : (d - 1) * CH;

    __shared__ __align__(16) float2 xs[32 * XK];  // [k2][r ^ (k2&14)] transposed
    __shared__ __align__(16) float2 ws[32 * WK];  // [k2][o_grp*10 + o_low]
    __shared__ float bs[CH];

    // ---- stage x: gmem-coalesced float4 loads, swizzled transpose ----
    #pragma unroll 4
    for (int it = 0; it < (ROWS * 16) / THREADS; ++it) {   // 32 iters
        int idx = tid + it * THREADS;          // 0..2047
        int r   = idx >> 4;                    // tile row (0..127)
        int c4  = idx & 15;                    // float4 index along k
        float4 v = *reinterpret_cast<const float4*>(
            x + (size_t)(row0 + r) * DIM + col0 + c4 * 4);
        int k2a = 2 * c4, k2b = 2 * c4 + 1;
        xs[k2a * XK + (r ^ (k2a & 14))] = make_float2(v.x, v.y);
        xs[k2b * XK + (r ^ (k2b & 14))] = make_float2(v.z, v.w);
    }

    // ---- stage weights (masked), k2-major with padded o-groups ----
    #pragma unroll
    for (int it = 0; it < (CH * 16) / THREADS; ++it) {     // 8 iters
        int idx = tid + it * THREADS;          // 0..511
        int o   = idx & 31;
        int c4  = idx >> 5;                    // 0..15
        size_t g = (size_t)(d * CH + o) * DIM + col0 + c4 * 4;
        float4 wv = *reinterpret_cast<const float4*>(w + g);
        float4 mv = *reinterpret_cast<const float4*>(mask + g);
        int wo = (o >> 3) * 10 + (o & 7);
        ws[(2 * c4)     * WK + wo] = make_float2(wv.x * mv.x, wv.y * mv.y);
        ws[(2 * c4 + 1) * WK + wo] = make_float2(wv.z * mv.z, wv.w * mv.w);
    }
    if (tid < CH) bs[tid] = bias[d * CH + tid];

    __syncthreads();

    // ---- compute: 8 rows x 8 outputs per thread ----
    const int lane  = tid & 31;
    const int warp  = tid >> 5;
    const int o_grp = lane & 3;               // 4 groups x 8 outputs
    const int r_grp = lane >> 2;              // 8 groups x 8 rows
    const int o0    = o_grp * 8;
    const int rbase = warp * 64 + r_grp * 8;  // full tile row base

    unsigned long long acc[8][8];             // [row][out] f32x2
    #pragma unroll
    for (int i = 0; i < 8; ++i)
        #pragma unroll
        for (int j = 0; j < 8; ++j) acc[i][j] = 0ull;

    #pragma unroll 4
    for (int k2 = 0; k2 < 32; ++k2) {
        const int s = k2 & 14;
        const float2* xb = &xs[k2 * XK];
        const float2* wb = &ws[k2 * WK + o_grp * 10];

        // weights for 8 outputs: 4 x LDS.128, bank-disjoint across o_grps
        unsigned long long wv[8];
        #pragma unroll
        for (int g = 0; g < 4; ++g) {
            ulonglong2 q = *reinterpret_cast<const ulonglong2*>(wb + 2 * g);
            wv[2 * g] = q.x; wv[2 * g + 1] = q.y;
        }
        // x for 8 rows: 4 x LDS.128 at swizzled granules.
        // FULL row id = rbase + 2t; s < 64 so warp*64 passes through the XOR.
        unsigned long long xv[8];
        #pragma unroll
        for (int t = 0; t < 4; ++t) {
            int u = (rbase + 2 * t) ^ s;
            ulonglong2 q = *reinterpret_cast<const ulonglong2*>(xb + u);
            xv[2 * t] = q.x; xv[2 * t + 1] = q.y;
        }
        #pragma unroll
        for (int i = 0; i < 8; ++i)
            #pragma unroll
            for (int j = 0; j < 8; ++j)
                ffma2(acc[i][j], xv[i], wv[j]);
    }

    // ---- epilogue: reduce halves, add bias, line-coalesced float4 stores ----
    #pragma unroll
    for (int i = 0; i < 8; ++i) {
        size_t rowg = (size_t)(row0 + rbase + i) * DIM + d * CH + o0;
        #pragma unroll
        for (int g = 0; g < 2; ++g) {
            float4 res;
            float* rp = reinterpret_cast<float*>(&res);
            #pragma unroll
            for (int c = 0; c < 4; ++c) {
                float2 a = *reinterpret_cast<float2*>(&acc[i][4 * g + c]);
                rp[c] = a.x + a.y + bs[o0 + 4 * g + c];
            }
            *reinterpret_cast<float4*>(out + rowg + 4 * g) = res;
        }
    }
}

extern "C" void kernel_launch(void* const* d_in, const int* in_sizes, int n_in,
                              void* d_out, int out_size) {
    const float* x    = (const float*)d_in[0];
    const float* w    = (const float*)d_in[1];
    const float* b    = (const float*)d_in[2];
    const float* m    = (const float*)d_in[3];
    float* out = (float*)d_out;

    dim3 grid(BATCH / ROWS, NODES);  // (256, 24)
    skeleton_linear_kernel<<<grid, THREADS>>>(x, w, b, m, out);
}